// round 5
// baseline (speedup 1.0000x reference)
#include <cuda_runtime.h>
#include <math.h>

#define DEV_INLINE __device__ __forceinline__

constexpr int Bb = 2, Ls = 1024, Dd = 1024, Hh = 16, HDd = 64;
constexpr int DINn = 2048, DTRr = 64;
constexpr int NROW = Bb * Ls;              // 2048
constexpr int QKVN = Dd + 2 * HDd;         // 1152

// ---------------- scratch arena (single __device__ array, no allocs) -------
constexpr long OFF_XN_M = 0;
constexpr long OFF_XN_A = OFF_XN_M + (long)NROW * Dd;
constexpr long OFF_XR   = OFF_XN_A + (long)NROW * Dd;              // [2048, 4096]
constexpr long OFF_U    = OFF_XR   + (long)NROW * 2 * DINn;        // [2048, 2048]
constexpr long OFF_DBC  = OFF_U    + (long)NROW * DINn;            // [2048, 96]
constexpr long OFF_DEL  = OFF_DBC  + (long)NROW * 96;              // [2048, 2048]
constexpr long OFF_Y    = OFF_DEL  + (long)NROW * DINn;            // [2048, 2048]
constexpr long OFF_MAM  = OFF_Y    + (long)NROW * DINn;            // [2048, 1024]
constexpr long OFF_QKV  = OFF_MAM  + (long)NROW * Dd;              // [2048, 1152]
constexpr long OFF_SC   = OFF_QKV  + (long)NROW * QKVN;            // [2,16,1024,1024]
constexpr long OFF_VT   = OFF_SC   + (long)Bb * Hh * Ls * Ls;      // [2, 64, 1024]
constexpr long OFF_O    = OFF_VT   + (long)Bb * HDd * Ls;          // [2048, 1024]
constexpr long OFF_ATTN = OFF_O    + (long)NROW * Dd;              // [2048, 1024]
constexpr long OFF_FUSE = OFF_ATTN + (long)NROW * Dd;              // [2048, 1024]
constexpr long SCRATCH_TOTAL = OFF_FUSE + (long)NROW * Dd;

__device__ float g_scratch[SCRATCH_TOTAL];

// ---------------- helpers --------------------------------------------------
DEV_INLINE float softplus_f(float x) {
    return (x > 20.f) ? x : log1pf(__expf(x));
}
DEV_INLINE float silu_f(float x) {
    return x / (1.f + __expf(-x));
}

DEV_INLINE float block_sum(float v, float* sh) {
    int lane = threadIdx.x & 31, wid = threadIdx.x >> 5;
    #pragma unroll
    for (int o = 16; o; o >>= 1) v += __shfl_xor_sync(0xffffffffu, v, o);
    __syncthreads();
    if (lane == 0) sh[wid] = v;
    __syncthreads();
    float r = 0.f;
    if (threadIdx.x < (blockDim.x >> 5)) r = sh[threadIdx.x];
    if (wid == 0) {
        #pragma unroll
        for (int o = 16; o; o >>= 1) r += __shfl_xor_sync(0xffffffffu, r, o);
        if (lane == 0) sh[32] = r;
    }
    __syncthreads();
    return sh[32];
}

DEV_INLINE float block_max(float v, float* sh) {
    int lane = threadIdx.x & 31, wid = threadIdx.x >> 5;
    #pragma unroll
    for (int o = 16; o; o >>= 1) v = fmaxf(v, __shfl_xor_sync(0xffffffffu, v, o));
    __syncthreads();
    if (lane == 0) sh[wid] = v;
    __syncthreads();
    float r = -3.4e38f;
    if (threadIdx.x < (blockDim.x >> 5)) r = sh[threadIdx.x];
    if (wid == 0) {
        #pragma unroll
        for (int o = 16; o; o >>= 1) r = fmaxf(r, __shfl_xor_sync(0xffffffffu, r, o));
        if (lane == 0) sh[32] = r;
    }
    __syncthreads();
    return sh[32];
}

// ---------------- dual LayerNorm (x -> xn_mamba, xn_attn) ------------------
__global__ void ln_dual(const float* __restrict__ x,
                        const float* __restrict__ w1, const float* __restrict__ b1,
                        const float* __restrict__ w2, const float* __restrict__ b2,
                        float* __restrict__ o1, float* __restrict__ o2) {
    __shared__ float sh[33];
    int row = blockIdx.x;
    const float4* xp = (const float4*)(x + (size_t)row * Dd);
    float4 v = xp[threadIdx.x];
    float s = v.x + v.y + v.z + v.w;
    s = block_sum(s, sh);
    float mean = s * (1.f / Dd);
    float4 c = make_float4(v.x - mean, v.y - mean, v.z - mean, v.w - mean);
    float s2 = c.x * c.x + c.y * c.y + c.z * c.z + c.w * c.w;
    s2 = block_sum(s2, sh);
    float rstd = rsqrtf(s2 * (1.f / Dd) + 1e-5f);
    int ci = threadIdx.x * 4;
    float4 W1 = *(const float4*)(w1 + ci);
    float4 B1 = *(const float4*)(b1 + ci);
    float4 out;
    out.x = c.x * rstd * W1.x + B1.x;
    out.y = c.y * rstd * W1.y + B1.y;
    out.z = c.z * rstd * W1.z + B1.z;
    out.w = c.w * rstd * W1.w + B1.w;
    ((float4*)(o1 + (size_t)row * Dd))[threadIdx.x] = out;
    if (o2) {
        float4 W2 = *(const float4*)(w2 + ci);
        float4 B2 = *(const float4*)(b2 + ci);
        float4 out2;
        out2.x = c.x * rstd * W2.x + B2.x;
        out2.y = c.y * rstd * W2.y + B2.y;
        out2.z = c.z * rstd * W2.z + B2.z;
        out2.w = c.w * rstd * W2.w + B2.w;
        ((float4*)(o2 + (size_t)row * Dd))[threadIdx.x] = out2;
    }
}

// ---------------- generic batched NT GEMM ---------------------------------
// C = scale * (A @ B^T) [+ bias(n)] [+ R] ; act: 0 none, 1 softplus
// batch index z decoded as (zo, zi) = (z / innerZ, z % innerZ); operand
// offsets are zo*s?o + zi*s?i. M must be a multiple of 128; K of 8.
__global__ void __launch_bounds__(256)
gemm_nt(const float* __restrict__ A, int lda, long sAo, long sAi,
        const float* __restrict__ B, int ldb, long sBo, long sBi,
        const float* __restrict__ bias,
        const float* __restrict__ R, int ldr, long sRo, long sRi,
        float* __restrict__ C, int ldc, long sCo, long sCi,
        int M, int N, int K, int innerZ, float scale, int act) {
    int zo = blockIdx.z / innerZ, zi = blockIdx.z % innerZ;
    A += zo * sAo + zi * sAi;
    B += zo * sBo + zi * sBi;
    C += zo * sCo + zi * sCi;
    if (R) R += zo * sRo + zi * sRi;

    __shared__ float As[8][128];
    __shared__ float Bs[8][128];

    int t = threadIdx.x;
    int tx = t & 15, ty = t >> 4;
    int mBase = blockIdx.y * 128, nBase = blockIdx.x * 128;
    int lrow = t >> 1, lcol = (t & 1) * 4;

    float acc[8][8];
    #pragma unroll
    for (int i = 0; i < 8; i++)
        #pragma unroll
        for (int j = 0; j < 8; j++) acc[i][j] = 0.f;

    const float* Aptr = A + (size_t)(mBase + lrow) * lda + lcol;
    const float* Bptr = B + (size_t)(nBase + lrow) * ldb + lcol;
    bool bvalid = (nBase + lrow) < N;

    for (int kt = 0; kt < K; kt += 8) {
        float4 av = *(const float4*)(Aptr + kt);
        float4 bv = make_float4(0.f, 0.f, 0.f, 0.f);
        if (bvalid) bv = *(const float4*)(Bptr + kt);
        As[lcol + 0][lrow] = av.x; As[lcol + 1][lrow] = av.y;
        As[lcol + 2][lrow] = av.z; As[lcol + 3][lrow] = av.w;
        Bs[lcol + 0][lrow] = bv.x; Bs[lcol + 1][lrow] = bv.y;
        Bs[lcol + 2][lrow] = bv.z; Bs[lcol + 3][lrow] = bv.w;
        __syncthreads();
        #pragma unroll
        for (int kk = 0; kk < 8; kk++) {
            float a[8], bb[8];
            #pragma unroll
            for (int i = 0; i < 8; i++) a[i] = As[kk][ty + i * 16];
            #pragma unroll
            for (int j = 0; j < 8; j++) bb[j] = Bs[kk][tx + j * 16];
            #pragma unroll
            for (int i = 0; i < 8; i++)
                #pragma unroll
                for (int j = 0; j < 8; j++)
                    acc[i][j] = fmaf(a[i], bb[j], acc[i][j]);
        }
        __syncthreads();
    }

    #pragma unroll
    for (int i = 0; i < 8; i++) {
        int m = mBase + ty + i * 16;
        #pragma unroll
        for (int j = 0; j < 8; j++) {
            int n = nBase + tx + j * 16;
            if (n < N) {
                float v = acc[i][j] * scale;
                if (bias) v += bias[n];
                if (R) v += R[(size_t)m * ldr + n];
                if (act == 1) v = softplus_f(v);
                C[(size_t)m * ldc + n] = v;
            }
        }
    }
}

// ---------------- depthwise causal conv (k=4) + SiLU -----------------------
__global__ void conv_silu_kernel(const float* __restrict__ xr, const float* __restrict__ w,
                                 const float* __restrict__ bias, float* __restrict__ u) {
    int idx = blockIdx.x * blockDim.x + threadIdx.x;
    if (idx >= NROW * DINn) return;
    int d = idx % DINn;
    int m = idx / DINn;
    int l = m % Ls;
    float acc = bias[d];
    #pragma unroll
    for (int j = 0; j < 4; j++) {
        int ls = l - 3 + j;
        if (ls >= 0)
            acc = fmaf(w[d * 4 + j], xr[(size_t)(m - 3 + j) * (2 * DINn) + d], acc);
    }
    u[idx] = silu_f(acc);
}

// ---------------- selective scan (+ u*D_skip, * silu(res)) -----------------
__global__ void scan_kernel(const float* __restrict__ delta, const float* __restrict__ u,
                            const float* __restrict__ dbc, const float* __restrict__ A_log,
                            const float* __restrict__ D_skip, const float* __restrict__ xr,
                            float* __restrict__ y) {
    int gid = blockIdx.x * blockDim.x + threadIdx.x;
    if (gid >= Bb * DINn) return;
    int b = gid / DINn, d = gid % DINn;
    float A[16];
    #pragma unroll
    for (int n = 0; n < 16; n++) A[n] = -__expf(A_log[d * 16 + n]);
    float Dsk = D_skip[d];
    float h[16];
    #pragma unroll
    for (int n = 0; n < 16; n++) h[n] = 0.f;
    for (int t = 0; t < Ls; t++) {
        size_t row = (size_t)b * Ls + t;
        float dt = delta[row * DINn + d];
        float uu = u[row * DINn + d];
        const float* bc = dbc + row * 96;
        float du = dt * uu;
        float acc = 0.f;
        #pragma unroll
        for (int n = 0; n < 16; n++) {
            float dA = __expf(dt * A[n]);
            h[n] = fmaf(dA, h[n], du * bc[64 + n]);
            acc = fmaf(h[n], bc[80 + n], acc);
        }
        acc = fmaf(uu, Dsk, acc);
        float r = xr[row * (2 * DINn) + DINn + d];
        y[row * DINn + d] = acc * silu_f(r);
    }
}

// ---------------- causal softmax over materialized scores ------------------
__global__ void softmax_causal(float* __restrict__ S) {
    __shared__ float sh[33];
    long row = blockIdx.x;                // Bb*Hh*Ls rows
    int l = (int)(row % Ls);
    int valid = l + 1;
    float* p = S + row * (long)Ls;
    float mx = -3.4e38f;
    for (int i = threadIdx.x; i < valid; i += blockDim.x) mx = fmaxf(mx, p[i]);
    mx = block_max(mx, sh);
    float sum = 0.f;
    for (int i = threadIdx.x; i < valid; i += blockDim.x) {
        float e = __expf(p[i] - mx);
        p[i] = e;
        sum += e;
    }
    sum = block_sum(sum, sh);
    float inv = 1.f / sum;
    for (int i = threadIdx.x; i < valid; i += blockDim.x) p[i] *= inv;
    for (int i = valid + threadIdx.x; i < Ls; i += blockDim.x) p[i] = 0.f;
}

// ---------------- V transpose ([B,L,HD] slice of qkv -> [B,HD,L]) ----------
__global__ void transpose_v(const float* __restrict__ qkv, float* __restrict__ vt) {
    int idx = blockIdx.x * blockDim.x + threadIdx.x;
    if (idx >= Bb * Ls * HDd) return;
    int d = idx % HDd;
    int l = (idx / HDd) % Ls;
    int b = idx / (HDd * Ls);
    vt[((size_t)b * HDd + d) * Ls + l] =
        qkv[((size_t)b * Ls + l) * QKVN + (Dd + HDd) + d];
}

// ---------------- host-side launcher ---------------------------------------
static inline void launch_gemm(const float* A, int lda, long sAo, long sAi,
                               const float* B, int ldb, long sBo, long sBi,
                               const float* bias,
                               const float* R, int ldr, long sRo, long sRi,
                               float* C, int ldc, long sCo, long sCi,
                               int M, int N, int K, int Z, int innerZ,
                               float scale, int act) {
    dim3 grid((N + 127) / 128, (M + 127) / 128, Z);
    gemm_nt<<<grid, 256>>>(A, lda, sAo, sAi, B, ldb, sBo, sBi, bias,
                           R, ldr, sRo, sRi, C, ldc, sCo, sCi,
                           M, N, K, innerZ, scale, act);
}

extern "C" void kernel_launch(void* const* d_in, const int* in_sizes, int n_in,
                              void* d_out, int out_size) {
    const float* x        = (const float*)d_in[0];
    const float* mnorm_w  = (const float*)d_in[1];
    const float* mnorm_b  = (const float*)d_in[2];
    const float* in_proj  = (const float*)d_in[3];
    const float* conv_w   = (const float*)d_in[4];
    const float* conv_b   = (const float*)d_in[5];
    const float* x_proj   = (const float*)d_in[6];
    const float* dt_proj  = (const float*)d_in[7];
    const float* dt_b     = (const float*)d_in[8];
    const float* A_log    = (const float*)d_in[9];
    const float* D_skip   = (const float*)d_in[10];
    const float* out_proj = (const float*)d_in[11];
    const float* norm1_w  = (const float*)d_in[12];
    const float* norm1_b  = (const float*)d_in[13];
    const float* wqkv_w   = (const float*)d_in[14];
    const float* wqkv_b   = (const float*)d_in[15];
    const float* oattn_w  = (const float*)d_in[16];
    const float* oattn_b  = (const float*)d_in[17];
    const float* fuse_w   = (const float*)d_in[18];
    const float* fuse_b   = (const float*)d_in[19];
    const float* fln_w    = (const float*)d_in[20];
    const float* fln_b    = (const float*)d_in[21];

    float* base = nullptr;
    cudaGetSymbolAddress((void**)&base, g_scratch);
    float* xn_m  = base + OFF_XN_M;
    float* xn_a  = base + OFF_XN_A;
    float* xr    = base + OFF_XR;
    float* u     = base + OFF_U;
    float* dbc   = base + OFF_DBC;
    float* delta = base + OFF_DEL;
    float* y     = base + OFF_Y;
    float* mamba = base + OFF_MAM;
    float* qkv   = base + OFF_QKV;
    float* S     = base + OFF_SC;
    float* vt    = base + OFF_VT;
    float* o     = base + OFF_O;
    float* attn  = base + OFF_ATTN;
    float* fuse  = base + OFF_FUSE;

    // 1. dual layernorm
    ln_dual<<<NROW, 256>>>(x, mnorm_w, mnorm_b, norm1_w, norm1_b, xn_m, xn_a);

    // 2. xr = xn_m @ in_proj^T              [2048, 4096]
    launch_gemm(xn_m, Dd, 0, 0, in_proj, Dd, 0, 0, nullptr,
                nullptr, 0, 0, 0, xr, 2 * DINn, 0, 0,
                NROW, 2 * DINn, Dd, 1, 1, 1.f, 0);

    // 3. depthwise conv + silu -> u         [2048, 2048]
    conv_silu_kernel<<<(NROW * DINn + 255) / 256, 256>>>(xr, conv_w, conv_b, u);

    // 4. dbc = u @ x_proj^T                 [2048, 96]
    launch_gemm(u, DINn, 0, 0, x_proj, DINn, 0, 0, nullptr,
                nullptr, 0, 0, 0, dbc, 96, 0, 0,
                NROW, 96, DINn, 1, 1, 1.f, 0);

    // 5. delta = softplus(dbc[:, :64] @ dt_proj^T + dt_b)   [2048, 2048]
    launch_gemm(dbc, 96, 0, 0, dt_proj, DTRr, 0, 0, dt_b,
                nullptr, 0, 0, 0, delta, DINn, 0, 0,
                NROW, DINn, DTRr, 1, 1, 1.f, 1);

    // 6. selective scan (incl. D_skip and * silu(res)) -> y
    scan_kernel<<<(Bb * DINn + 127) / 128, 128>>>(delta, u, dbc, A_log, D_skip, xr, y);

    // 7. mamba_out = y @ out_proj^T + x     [2048, 1024]
    launch_gemm(y, DINn, 0, 0, out_proj, DINn, 0, 0, nullptr,
                x, Dd, 0, 0, mamba, Dd, 0, 0,
                NROW, Dd, DINn, 1, 1, 1.f, 0);

    // 8. qkv = xn_a @ wqkv^T + wqkv_b       [2048, 1152]
    launch_gemm(xn_a, Dd, 0, 0, wqkv_w, Dd, 0, 0, wqkv_b,
                nullptr, 0, 0, 0, qkv, QKVN, 0, 0,
                NROW, QKVN, Dd, 1, 1, 1.f, 0);

    // 9. scores = q @ k^T / 8, batched over (b,h)   [2,16,1024,1024]
    launch_gemm(qkv, QKVN, (long)Ls * QKVN, 64,
                qkv + Dd, QKVN, (long)Ls * QKVN, 0,
                nullptr, nullptr, 0, 0, 0,
                S, Ls, (long)Hh * Ls * Ls, (long)Ls * Ls,
                Ls, Ls, HDd, Bb * Hh, Hh, 0.125f, 0);

    // 10. causal softmax in-place
    softmax_causal<<<Bb * Hh * Ls, 256>>>(S);

    // 11. V transpose for NT GEMM
    transpose_v<<<(Bb * Ls * HDd + 255) / 256, 256>>>(qkv, vt);

    // 12. o = P @ V, batched over (b,h)     -> [2048, 1024] (col block h*64)
    launch_gemm(S, Ls, (long)Hh * Ls * Ls, (long)Ls * Ls,
                vt, Ls, (long)HDd * Ls, 0,
                nullptr, nullptr, 0, 0, 0,
                o, Dd, (long)Ls * Dd, 64,
                Ls, HDd, Ls, Bb * Hh, Hh, 1.f, 0);

    // 13. attn_out = o @ oattn^T + oattn_b + x
    launch_gemm(o, Dd, 0, 0, oattn_w, Dd, 0, 0, oattn_b,
                x, Dd, 0, 0, attn, Dd, 0, 0,
                NROW, Dd, Dd, 1, 1, 1.f, 0);

    // 14. fuse_pre = mamba @ fuse_w[:, :D]^T + fuse_b
    launch_gemm(mamba, Dd, 0, 0, fuse_w, 2 * Dd, 0, 0, fuse_b,
                nullptr, 0, 0, 0, fuse, Dd, 0, 0,
                NROW, Dd, Dd, 1, 1, 1.f, 0);

    // 15. fuse_pre += attn @ fuse_w[:, D:]^T  (R = fuse accumulates step 14)
    launch_gemm(attn, Dd, 0, 0, fuse_w + Dd, 2 * Dd, 0, 0, nullptr,
                fuse, Dd, 0, 0, fuse, Dd, 0, 0,
                NROW, Dd, Dd, 1, 1, 1.f, 0);

    // 16. final layernorm -> d_out
    ln_dual<<<NROW, 256>>>(fuse, fln_w, fln_b, nullptr, nullptr,
                           (float*)d_out, nullptr);
}

// round 8
// speedup vs baseline: 1.6924x; 1.6924x over previous
#include <cuda_runtime.h>
#include <math.h>
#include <stdint.h>

#define DEV_INLINE __device__ __forceinline__

constexpr int Bb = 2, Ls = 1024, Dd = 1024, Hh = 16, HDd = 64;
constexpr int DINn = 2048, DTRr = 64;
constexpr int NROW = Bb * Ls;              // 2048
constexpr int QKVN = Dd + 2 * HDd;         // 1152

// ---------------- scratch arena (single __device__ array, no allocs) -------
constexpr long OFF_XN_M = 0;
constexpr long OFF_XN_A = OFF_XN_M + (long)NROW * Dd;
constexpr long OFF_XR   = OFF_XN_A + (long)NROW * Dd;              // [2048, 4096]
constexpr long OFF_U    = OFF_XR   + (long)NROW * 2 * DINn;        // [2048, 2048]
constexpr long OFF_DBC  = OFF_U    + (long)NROW * DINn;            // [2048, 96]
constexpr long OFF_DEL  = OFF_DBC  + (long)NROW * 96;              // [2048, 2048]
constexpr long OFF_Y    = OFF_DEL  + (long)NROW * DINn;            // [2048, 2048]
constexpr long OFF_MAM  = OFF_Y    + (long)NROW * DINn;            // [2048, 1024]
constexpr long OFF_QKV  = OFF_MAM  + (long)NROW * Dd;              // [2048, 1152]
constexpr long OFF_SC   = OFF_QKV  + (long)NROW * QKVN;            // [2,16,1024,1024] (also dbc split-K partials)
constexpr long OFF_VT   = OFF_SC   + (long)Bb * Hh * Ls * Ls;      // [2, 64, 1024]
constexpr long OFF_O    = OFF_VT   + (long)Bb * HDd * Ls;          // [2048, 1024]
constexpr long OFF_ATTN = OFF_O    + (long)NROW * Dd;              // [2048, 1024]
constexpr long OFF_FUSE = OFF_ATTN + (long)NROW * Dd;              // [2048, 1024]
constexpr long SCRATCH_TOTAL = OFF_FUSE + (long)NROW * Dd;

__device__ float g_scratch[SCRATCH_TOTAL];

// ---------------- helpers --------------------------------------------------
DEV_INLINE float softplus_f(float x) {
    return (x > 20.f) ? x : log1pf(__expf(x));
}
DEV_INLINE float silu_f(float x) {
    return x / (1.f + __expf(-x));
}

DEV_INLINE float block_sum(float v, float* sh) {
    int lane = threadIdx.x & 31, wid = threadIdx.x >> 5;
    #pragma unroll
    for (int o = 16; o; o >>= 1) v += __shfl_xor_sync(0xffffffffu, v, o);
    __syncthreads();
    if (lane == 0) sh[wid] = v;
    __syncthreads();
    float r = 0.f;
    if (threadIdx.x < (blockDim.x >> 5)) r = sh[threadIdx.x];
    if (wid == 0) {
        #pragma unroll
        for (int o = 16; o; o >>= 1) r += __shfl_xor_sync(0xffffffffu, r, o);
        if (lane == 0) sh[32] = r;
    }
    __syncthreads();
    return sh[32];
}

DEV_INLINE float block_max(float v, float* sh) {
    int lane = threadIdx.x & 31, wid = threadIdx.x >> 5;
    #pragma unroll
    for (int o = 16; o; o >>= 1) v = fmaxf(v, __shfl_xor_sync(0xffffffffu, v, o));
    __syncthreads();
    if (lane == 0) sh[wid] = v;
    __syncthreads();
    float r = -3.4e38f;
    if (threadIdx.x < (blockDim.x >> 5)) r = sh[threadIdx.x];
    if (wid == 0) {
        #pragma unroll
        for (int o = 16; o; o >>= 1) r = fmaxf(r, __shfl_xor_sync(0xffffffffu, r, o));
        if (lane == 0) sh[32] = r;
    }
    __syncthreads();
    return sh[32];
}

DEV_INLINE uint32_t f2tf32(float x) {
    uint32_t r;
    asm("cvt.rna.tf32.f32 %0, %1;" : "=r"(r) : "f"(x));
    return r;
}

DEV_INLINE void mma_tf32(float* c, const uint32_t* a, const uint32_t* b) {
    asm volatile(
        "mma.sync.aligned.m16n8k8.row.col.f32.tf32.tf32.f32 "
        "{%0,%1,%2,%3}, {%4,%5,%6,%7}, {%8,%9}, {%0,%1,%2,%3};\n"
        : "+f"(c[0]), "+f"(c[1]), "+f"(c[2]), "+f"(c[3])
        : "r"(a[0]), "r"(a[1]), "r"(a[2]), "r"(a[3]),
          "r"(b[0]), "r"(b[1]));
}

// ---------------- dual LayerNorm (x -> xn_mamba, xn_attn) ------------------
__global__ void ln_dual(const float* __restrict__ x,
                        const float* __restrict__ w1, const float* __restrict__ b1,
                        const float* __restrict__ w2, const float* __restrict__ b2,
                        float* __restrict__ o1, float* __restrict__ o2) {
    __shared__ float sh[33];
    int row = blockIdx.x;
    const float4* xp = (const float4*)(x + (size_t)row * Dd);
    float4 v = xp[threadIdx.x];
    float s = v.x + v.y + v.z + v.w;
    s = block_sum(s, sh);
    float mean = s * (1.f / Dd);
    float4 c = make_float4(v.x - mean, v.y - mean, v.z - mean, v.w - mean);
    float s2 = c.x * c.x + c.y * c.y + c.z * c.z + c.w * c.w;
    s2 = block_sum(s2, sh);
    float rstd = rsqrtf(s2 * (1.f / Dd) + 1e-5f);
    int ci = threadIdx.x * 4;
    float4 W1 = *(const float4*)(w1 + ci);
    float4 B1 = *(const float4*)(b1 + ci);
    float4 out;
    out.x = c.x * rstd * W1.x + B1.x;
    out.y = c.y * rstd * W1.y + B1.y;
    out.z = c.z * rstd * W1.z + B1.z;
    out.w = c.w * rstd * W1.w + B1.w;
    ((float4*)(o1 + (size_t)row * Dd))[threadIdx.x] = out;
    if (o2) {
        float4 W2 = *(const float4*)(w2 + ci);
        float4 B2 = *(const float4*)(b2 + ci);
        float4 out2;
        out2.x = c.x * rstd * W2.x + B2.x;
        out2.y = c.y * rstd * W2.y + B2.y;
        out2.z = c.z * rstd * W2.z + B2.z;
        out2.w = c.w * rstd * W2.w + B2.w;
        ((float4*)(o2 + (size_t)row * Dd))[threadIdx.x] = out2;
    }
}

// ---------------- TF32 tensor-core batched NT GEMM -------------------------
// C = scale * (A @ B^T) [+ bias(n)] [+ R]
// Tiles: 128x128x16, 8 warps of 64x32 (m16n8k8 mma), double-buffered smem.
// Requires: M % 128 == 0, K % 16 == 0. N tail handled by guards.
constexpr int TPAD = 136;   // bank = 8*tg + g pattern => conflict-free frag LDS

__global__ void __launch_bounds__(256, 2)
gemm_tf32(const float* __restrict__ A, int lda, long sAo, long sAi,
          const float* __restrict__ B, int ldb, long sBo, long sBi,
          const float* __restrict__ bias,
          const float* __restrict__ R, int ldr, long sRo, long sRi,
          float* __restrict__ C, int ldc, long sCo, long sCi,
          int M, int N, int K, int innerZ, float scale) {
    int zo = blockIdx.z / innerZ, zi = blockIdx.z % innerZ;
    A += zo * sAo + zi * sAi;
    B += zo * sBo + zi * sBi;
    C += zo * sCo + zi * sCi;
    if (R) R += zo * sRo + zi * sRi;

    __shared__ uint32_t As[2][16 * TPAD];
    __shared__ uint32_t Bs[2][16 * TPAD];

    int t = threadIdx.x;
    int lane = t & 31, wid = t >> 5;
    int warpM = wid & 1, warpN = wid >> 1;       // 2 x 4 warps
    int g = lane >> 2, tg = lane & 3;
    int mBase = blockIdx.y * 128, nBase = blockIdx.x * 128;

    // loader: thread -> (row = t>>1, 8 contiguous k at (t&1)*8)
    int lrow = t >> 1;
    int lcol = (t & 1) * 8;
    const float* Ag = A + (size_t)(mBase + lrow) * lda + lcol;
    const float* Bg = B + (size_t)(nBase + lrow) * ldb + lcol;
    bool bvalid = (nBase + lrow) < N;

    float acc[4][4][4];
    #pragma unroll
    for (int i = 0; i < 4; i++)
        #pragma unroll
        for (int j = 0; j < 4; j++)
            #pragma unroll
            for (int c = 0; c < 4; c++) acc[i][j][c] = 0.f;

    float4 a0, a1, b0, b1;

    auto gload = [&](int kt) {
        a0 = *(const float4*)(Ag + kt);
        a1 = *(const float4*)(Ag + kt + 4);
        if (bvalid) {
            b0 = *(const float4*)(Bg + kt);
            b1 = *(const float4*)(Bg + kt + 4);
        } else {
            b0 = make_float4(0.f, 0.f, 0.f, 0.f);
            b1 = b0;
        }
    };
    auto stage = [&](int buf) {
        uint32_t* as = As[buf];
        uint32_t* bs = Bs[buf];
        const float* af = (const float*)&a0;
        const float* ag2 = (const float*)&a1;
        const float* bf = (const float*)&b0;
        const float* bg2 = (const float*)&b1;
        #pragma unroll
        for (int c = 0; c < 4; c++) {
            as[(lcol + c) * TPAD + lrow]     = f2tf32(af[c]);
            as[(lcol + c + 4) * TPAD + lrow] = f2tf32(ag2[c]);
            bs[(lcol + c) * TPAD + lrow]     = f2tf32(bf[c]);
            bs[(lcol + c + 4) * TPAD + lrow] = f2tf32(bg2[c]);
        }
    };
    auto compute = [&](int buf) {
        const uint32_t* as = As[buf];
        const uint32_t* bs = Bs[buf];
        #pragma unroll
        for (int k0 = 0; k0 < 16; k0 += 8) {
            uint32_t af[4][4], bf[4][2];
            #pragma unroll
            for (int i = 0; i < 4; i++) {
                int m0 = warpM * 64 + i * 16 + g;
                af[i][0] = as[(k0 + tg) * TPAD + m0];
                af[i][1] = as[(k0 + tg) * TPAD + m0 + 8];
                af[i][2] = as[(k0 + tg + 4) * TPAD + m0];
                af[i][3] = as[(k0 + tg + 4) * TPAD + m0 + 8];
            }
            #pragma unroll
            for (int j = 0; j < 4; j++) {
                int n0 = warpN * 32 + j * 8 + g;
                bf[j][0] = bs[(k0 + tg) * TPAD + n0];
                bf[j][1] = bs[(k0 + tg + 4) * TPAD + n0];
            }
            #pragma unroll
            for (int i = 0; i < 4; i++)
                #pragma unroll
                for (int j = 0; j < 4; j++)
                    mma_tf32(acc[i][j], af[i], bf[j]);
        }
    };

    int nc = K >> 4;
    gload(0);
    stage(0);
    for (int kt = 1; kt < nc; kt++) {
        __syncthreads();
        gload(kt * 16);
        compute((kt - 1) & 1);
        stage(kt & 1);
    }
    __syncthreads();
    compute((nc - 1) & 1);

    // epilogue
    #pragma unroll
    for (int i = 0; i < 4; i++) {
        int m = mBase + warpM * 64 + i * 16 + g;
        #pragma unroll
        for (int j = 0; j < 4; j++) {
            int n = nBase + warpN * 32 + j * 8 + 2 * tg;
            if (n < N) {
                float2 v0 = make_float2(acc[i][j][0] * scale, acc[i][j][1] * scale);
                float2 v1 = make_float2(acc[i][j][2] * scale, acc[i][j][3] * scale);
                if (bias) {
                    float2 bb = *(const float2*)(bias + n);
                    v0.x += bb.x; v0.y += bb.y;
                    v1.x += bb.x; v1.y += bb.y;
                }
                if (R) {
                    float2 r0 = *(const float2*)(R + (size_t)m * ldr + n);
                    float2 r1 = *(const float2*)(R + (size_t)(m + 8) * ldr + n);
                    v0.x += r0.x; v0.y += r0.y;
                    v1.x += r1.x; v1.y += r1.y;
                }
                *(float2*)(C + (size_t)m * ldc + n) = v0;
                *(float2*)(C + (size_t)(m + 8) * ldc + n) = v1;
            }
        }
    }
}

// ---------------- generic batched NT GEMM (fp32, precision-critical) -------
__global__ void __launch_bounds__(256)
gemm_nt(const float* __restrict__ A, int lda, long sAo, long sAi,
        const float* __restrict__ B, int ldb, long sBo, long sBi,
        const float* __restrict__ bias,
        const float* __restrict__ R, int ldr, long sRo, long sRi,
        float* __restrict__ C, int ldc, long sCo, long sCi,
        int M, int N, int K, int innerZ, float scale, int act) {
    int zo = blockIdx.z / innerZ, zi = blockIdx.z % innerZ;
    A += zo * sAo + zi * sAi;
    B += zo * sBo + zi * sBi;
    C += zo * sCo + zi * sCi;
    if (R) R += zo * sRo + zi * sRi;

    __shared__ float As[8][128];
    __shared__ float Bs[8][128];

    int t = threadIdx.x;
    int tx = t & 15, ty = t >> 4;
    int mBase = blockIdx.y * 128, nBase = blockIdx.x * 128;
    int lrow = t >> 1, lcol = (t & 1) * 4;

    float acc[8][8];
    #pragma unroll
    for (int i = 0; i < 8; i++)
        #pragma unroll
        for (int j = 0; j < 8; j++) acc[i][j] = 0.f;

    const float* Aptr = A + (size_t)(mBase + lrow) * lda + lcol;
    const float* Bptr = B + (size_t)(nBase + lrow) * ldb + lcol;
    bool bvalid = (nBase + lrow) < N;

    for (int kt = 0; kt < K; kt += 8) {
        float4 av = *(const float4*)(Aptr + kt);
        float4 bv = make_float4(0.f, 0.f, 0.f, 0.f);
        if (bvalid) bv = *(const float4*)(Bptr + kt);
        As[lcol + 0][lrow] = av.x; As[lcol + 1][lrow] = av.y;
        As[lcol + 2][lrow] = av.z; As[lcol + 3][lrow] = av.w;
        Bs[lcol + 0][lrow] = bv.x; Bs[lcol + 1][lrow] = bv.y;
        Bs[lcol + 2][lrow] = bv.z; Bs[lcol + 3][lrow] = bv.w;
        __syncthreads();
        #pragma unroll
        for (int kk = 0; kk < 8; kk++) {
            float a[8], bb[8];
            #pragma unroll
            for (int i = 0; i < 8; i++) a[i] = As[kk][ty + i * 16];
            #pragma unroll
            for (int j = 0; j < 8; j++) bb[j] = Bs[kk][tx + j * 16];
            #pragma unroll
            for (int i = 0; i < 8; i++)
                #pragma unroll
                for (int j = 0; j < 8; j++)
                    acc[i][j] = fmaf(a[i], bb[j], acc[i][j]);
        }
        __syncthreads();
    }

    #pragma unroll
    for (int i = 0; i < 8; i++) {
        int m = mBase + ty + i * 16;
        #pragma unroll
        for (int j = 0; j < 8; j++) {
            int n = nBase + tx + j * 16;
            if (n < N) {
                float v = acc[i][j] * scale;
                if (bias) v += bias[n];
                if (R) v += R[(size_t)m * ldr + n];
                if (act == 1) v = softplus_f(v);
                C[(size_t)m * ldc + n] = v;
            }
        }
    }
}

// ---------------- dbc split-K reduction ------------------------------------
__global__ void reduce_dbc(const float* __restrict__ part, float* __restrict__ out) {
    int i = blockIdx.x * blockDim.x + threadIdx.x;
    if (i >= NROW * 96) return;
    float s = 0.f;
    #pragma unroll
    for (int k = 0; k < 16; k++) s += part[(long)k * NROW * 96 + i];
    out[i] = s;
}

// ---------------- depthwise causal conv (k=4) + SiLU -----------------------
__global__ void conv_silu_kernel(const float* __restrict__ xr, const float* __restrict__ w,
                                 const float* __restrict__ bias, float* __restrict__ u) {
    int idx = blockIdx.x * blockDim.x + threadIdx.x;
    if (idx >= NROW * DINn) return;
    int d = idx % DINn;
    int m = idx / DINn;
    int l = m % Ls;
    float acc = bias[d];
    #pragma unroll
    for (int j = 0; j < 4; j++) {
        int ls = l - 3 + j;
        if (ls >= 0)
            acc = fmaf(w[d * 4 + j], xr[(size_t)(m - 3 + j) * (2 * DINn) + d], acc);
    }
    u[idx] = silu_f(acc);
}

// ---------------- selective scan (+ u*D_skip, * silu(res)) -----------------
__global__ void scan_kernel(const float* __restrict__ delta, const float* __restrict__ u,
                            const float* __restrict__ dbc, const float* __restrict__ A_log,
                            const float* __restrict__ D_skip, const float* __restrict__ xr,
                            float* __restrict__ y) {
    int gid = blockIdx.x * blockDim.x + threadIdx.x;
    if (gid >= Bb * DINn) return;
    int b = gid / DINn, d = gid % DINn;
    float A[16];
    #pragma unroll
    for (int n = 0; n < 16; n++) A[n] = -__expf(A_log[d * 16 + n]);
    float Dsk = D_skip[d];
    float h[16];
    #pragma unroll
    for (int n = 0; n < 16; n++) h[n] = 0.f;
    for (int t = 0; t < Ls; t++) {
        size_t row = (size_t)b * Ls + t;
        float dt = delta[row * DINn + d];
        float uu = u[row * DINn + d];
        const float* bc = dbc + row * 96;
        float du = dt * uu;
        float acc = 0.f;
        #pragma unroll
        for (int n = 0; n < 16; n++) {
            float dA = __expf(dt * A[n]);
            h[n] = fmaf(dA, h[n], du * bc[64 + n]);
            acc = fmaf(h[n], bc[80 + n], acc);
        }
        acc = fmaf(uu, Dsk, acc);
        float r = xr[row * (2 * DINn) + DINn + d];
        y[row * DINn + d] = acc * silu_f(r);
    }
}

// ---------------- causal softmax over materialized scores ------------------
__global__ void softmax_causal(float* __restrict__ S) {
    __shared__ float sh[33];
    long row = blockIdx.x;                // Bb*Hh*Ls rows
    int l = (int)(row % Ls);
    int valid = l + 1;
    float* p = S + row * (long)Ls;
    float mx = -3.4e38f;
    for (int i = threadIdx.x; i < valid; i += blockDim.x) mx = fmaxf(mx, p[i]);
    mx = block_max(mx, sh);
    float sum = 0.f;
    for (int i = threadIdx.x; i < valid; i += blockDim.x) {
        float e = __expf(p[i] - mx);
        p[i] = e;
        sum += e;
    }
    sum = block_sum(sum, sh);
    float inv = 1.f / sum;
    for (int i = threadIdx.x; i < valid; i += blockDim.x) p[i] *= inv;
    for (int i = valid + threadIdx.x; i < Ls; i += blockDim.x) p[i] = 0.f;
}

// ---------------- V transpose ([B,L,HD] slice of qkv -> [B,HD,L]) ----------
__global__ void transpose_v(const float* __restrict__ qkv, float* __restrict__ vt) {
    int idx = blockIdx.x * blockDim.x + threadIdx.x;
    if (idx >= Bb * Ls * HDd) return;
    int d = idx % HDd;
    int l = (idx / HDd) % Ls;
    int b = idx / (HDd * Ls);
    vt[((size_t)b * HDd + d) * Ls + l] =
        qkv[((size_t)b * Ls + l) * QKVN + (Dd + HDd) + d];
}

// ---------------- host-side launchers ---------------------------------------
static inline void launch_gemm(const float* A, int lda, long sAo, long sAi,
                               const float* B, int ldb, long sBo, long sBi,
                               const float* bias,
                               const float* R, int ldr, long sRo, long sRi,
                               float* C, int ldc, long sCo, long sCi,
                               int M, int N, int K, int Z, int innerZ,
                               float scale, int act) {
    dim3 grid((N + 127) / 128, (M + 127) / 128, Z);
    gemm_nt<<<grid, 256>>>(A, lda, sAo, sAi, B, ldb, sBo, sBi, bias,
                           R, ldr, sRo, sRi, C, ldc, sCo, sCi,
                           M, N, K, innerZ, scale, act);
}

static inline void launch_tf32(const float* A, int lda, long sAo, long sAi,
                               const float* B, int ldb, long sBo, long sBi,
                               const float* bias,
                               const float* R, int ldr, long sRo, long sRi,
                               float* C, int ldc, long sCo, long sCi,
                               int M, int N, int K, int Z, int innerZ,
                               float scale) {
    dim3 grid((N + 127) / 128, (M + 127) / 128, Z);
    gemm_tf32<<<grid, 256>>>(A, lda, sAo, sAi, B, ldb, sBo, sBi, bias,
                             R, ldr, sRo, sRi, C, ldc, sCo, sCi,
                             M, N, K, innerZ, scale);
}

extern "C" void kernel_launch(void* const* d_in, const int* in_sizes, int n_in,
                              void* d_out, int out_size) {
    const float* x        = (const float*)d_in[0];
    const float* mnorm_w  = (const float*)d_in[1];
    const float* mnorm_b  = (const float*)d_in[2];
    const float* in_proj  = (const float*)d_in[3];
    const float* conv_w   = (const float*)d_in[4];
    const float* conv_b   = (const float*)d_in[5];
    const float* x_proj   = (const float*)d_in[6];
    const float* dt_proj  = (const float*)d_in[7];
    const float* dt_b     = (const float*)d_in[8];
    const float* A_log    = (const float*)d_in[9];
    const float* D_skip   = (const float*)d_in[10];
    const float* out_proj = (const float*)d_in[11];
    const float* norm1_w  = (const float*)d_in[12];
    const float* norm1_b  = (const float*)d_in[13];
    const float* wqkv_w   = (const float*)d_in[14];
    const float* wqkv_b   = (const float*)d_in[15];
    const float* oattn_w  = (const float*)d_in[16];
    const float* oattn_b  = (const float*)d_in[17];
    const float* fuse_w   = (const float*)d_in[18];
    const float* fuse_b   = (const float*)d_in[19];
    const float* fln_w    = (const float*)d_in[20];
    const float* fln_b    = (const float*)d_in[21];

    float* base = nullptr;
    cudaGetSymbolAddress((void**)&base, g_scratch);
    float* xn_m  = base + OFF_XN_M;
    float* xn_a  = base + OFF_XN_A;
    float* xr    = base + OFF_XR;
    float* u     = base + OFF_U;
    float* dbc   = base + OFF_DBC;
    float* delta = base + OFF_DEL;
    float* y     = base + OFF_Y;
    float* mamba = base + OFF_MAM;
    float* qkv   = base + OFF_QKV;
    float* S     = base + OFF_SC;
    float* vt    = base + OFF_VT;
    float* o     = base + OFF_O;
    float* attn  = base + OFF_ATTN;
    float* fuse  = base + OFF_FUSE;

    // 1. dual layernorm
    ln_dual<<<NROW, 256>>>(x, mnorm_w, mnorm_b, norm1_w, norm1_b, xn_m, xn_a);

    // 2. xr = xn_m @ in_proj^T              [2048, 4096]  (TF32)
    launch_tf32(xn_m, Dd, 0, 0, in_proj, Dd, 0, 0, nullptr,
                nullptr, 0, 0, 0, xr, 2 * DINn, 0, 0,
                NROW, 2 * DINn, Dd, 1, 1, 1.f);

    // 3. depthwise conv + silu -> u         [2048, 2048]
    conv_silu_kernel<<<(NROW * DINn + 255) / 256, 256>>>(xr, conv_w, conv_b, u);

    // 4a. dbc partials via deterministic split-K (fp32 FFMA, 16 slices of K=128)
    //     partial[s] = u[:, s*128:(s+1)*128] @ x_proj[:, s*128:(s+1)*128]^T
    launch_gemm(u, DINn, 128, 0, x_proj, DINn, 128, 0, nullptr,
                nullptr, 0, 0, 0, S /*partials*/, 96, (long)NROW * 96, 0,
                NROW, 96, 128, 16, 1, 1.f, 0);
    // 4b. reduce 16 partials -> dbc
    reduce_dbc<<<(NROW * 96 + 255) / 256, 256>>>(S, dbc);

    // 5. delta = softplus(dbc[:, :64] @ dt_proj^T + dt_b)   (fp32 FFMA, K=64)
    launch_gemm(dbc, 96, 0, 0, dt_proj, DTRr, 0, 0, dt_b,
                nullptr, 0, 0, 0, delta, DINn, 0, 0,
                NROW, DINn, DTRr, 1, 1, 1.f, 1);

    // 6. selective scan (incl. D_skip and * silu(res)) -> y
    scan_kernel<<<(Bb * DINn + 127) / 128, 128>>>(delta, u, dbc, A_log, D_skip, xr, y);

    // 7. mamba_out = y @ out_proj^T + x     [2048, 1024]  (TF32)
    launch_tf32(y, DINn, 0, 0, out_proj, DINn, 0, 0, nullptr,
                x, Dd, 0, 0, mamba, Dd, 0, 0,
                NROW, Dd, DINn, 1, 1, 1.f);

    // 8. qkv = xn_a @ wqkv^T + wqkv_b       [2048, 1152]  (TF32)
    launch_tf32(xn_a, Dd, 0, 0, wqkv_w, Dd, 0, 0, wqkv_b,
                nullptr, 0, 0, 0, qkv, QKVN, 0, 0,
                NROW, QKVN, Dd, 1, 1, 1.f);

    // 9. scores = q @ k^T / 8, batched over (b,h)   [2,16,1024,1024]  (TF32)
    launch_tf32(qkv, QKVN, (long)Ls * QKVN, 64,
                qkv + Dd, QKVN, (long)Ls * QKVN, 0,
                nullptr, nullptr, 0, 0, 0,
                S, Ls, (long)Hh * Ls * Ls, (long)Ls * Ls,
                Ls, Ls, HDd, Bb * Hh, Hh, 0.125f);

    // 10. causal softmax in-place
    softmax_causal<<<Bb * Hh * Ls, 256>>>(S);

    // 11. V transpose for NT GEMM
    transpose_v<<<(Bb * Ls * HDd + 255) / 256, 256>>>(qkv, vt);

    // 12. o = P @ V, batched over (b,h)     -> [2048, 1024]  (TF32)
    launch_tf32(S, Ls, (long)Hh * Ls * Ls, (long)Ls * Ls,
                vt, Ls, (long)HDd * Ls, 0,
                nullptr, nullptr, 0, 0, 0,
                o, Dd, (long)Ls * Dd, 64,
                Ls, HDd, Ls, Bb * Hh, Hh, 1.f);

    // 13. attn_out = o @ oattn^T + oattn_b + x   (TF32)
    launch_tf32(o, Dd, 0, 0, oattn_w, Dd, 0, 0, oattn_b,
                x, Dd, 0, 0, attn, Dd, 0, 0,
                NROW, Dd, Dd, 1, 1, 1.f);

    // 14. fuse_pre = mamba @ fuse_w[:, :D]^T + fuse_b   (TF32)
    launch_tf32(mamba, Dd, 0, 0, fuse_w, 2 * Dd, 0, 0, fuse_b,
                nullptr, 0, 0, 0, fuse, Dd, 0, 0,
                NROW, Dd, Dd, 1, 1, 1.f);

    // 15. fuse_pre += attn @ fuse_w[:, D:]^T  (R = fuse accumulates step 14)
    launch_tf32(attn, Dd, 0, 0, fuse_w + Dd, 2 * Dd, 0, 0, nullptr,
                fuse, Dd, 0, 0, fuse, Dd, 0, 0,
                NROW, Dd, Dd, 1, 1, 1.f);

    // 16. final layernorm -> d_out
    ln_dual<<<NROW, 256>>>(fuse, fln_w, fln_b, nullptr, nullptr,
                           (float*)d_out, nullptr);
}